// round 1
// baseline (speedup 1.0000x reference)
#include <cuda_runtime.h>
#include <math.h>

#define B_    8
#define KB_   16
#define SEQ_  512
#define HID_  768
#define NPAIR (B_ * KB_)         // 128
#define STILES (SEQ_ / 64)       // 8

// ---------------- scratch (static device arrays; no allocation) ----------------
__device__ float g_qn[B_ * SEQ_ * HID_];        // 12.6 MB normalized queries
__device__ float g_kn[KB_ * SEQ_ * HID_];       // 25.2 MB normalized keys
__device__ float g_partial[NPAIR * STILES];     // per (pair, s-tile) partial sums

#define NEG_BIG (-3.0e38f)

// ---------------- kernel 0: row L2 normalize ----------------
// one block per row of 768 floats; 192 threads x float4
__global__ __launch_bounds__(192) void norm_rows(const float* __restrict__ in, int which) {
    float* __restrict__ outbase = which ? g_kn : g_qn;
    const long row = blockIdx.x;
    const float4* src = (const float4*)(in + row * (long)HID_);
    float4* dst = (float4*)(outbase + row * (long)HID_);
    int t = threadIdx.x;

    float4 v = src[t];
    float s = v.x * v.x + v.y * v.y + v.z * v.z + v.w * v.w;
    #pragma unroll
    for (int o = 16; o; o >>= 1) s += __shfl_xor_sync(0xffffffffu, s, o);

    __shared__ float red[6];
    __shared__ float scale_sh;
    if ((t & 31) == 0) red[t >> 5] = s;
    __syncthreads();
    if (t == 0) {
        float tot = 0.f;
        #pragma unroll
        for (int w = 0; w < 6; w++) tot += red[w];
        scale_sh = 1.0f / fmaxf(sqrtf(tot), 1e-12f);
    }
    __syncthreads();
    float sc = scale_sh;
    dst[t] = make_float4(v.x * sc, v.y * sc, v.z * sc, v.w * sc);
}

// ---------------- kernel 1: fused batched GEMM + online softmax ----------------
// grid = (STILES, NPAIR), 256 threads.
// block computes C[64 s-rows][512 t] for pair (i,j) in 64-col tiles,
// maintaining per-row online softmax state; value == cosine sim itself.
__global__ __launch_bounds__(256, 2) void li_main(const float* __restrict__ alpha_p,
                                                  const int*   __restrict__ qmask,
                                                  const int*   __restrict__ kmask) {
    __shared__ float As[16][68];
    __shared__ float Bs[16][68];
    __shared__ float Cs[64][68];
    __shared__ float dtab[SEQ_];
    __shared__ int   km[SEQ_];
    __shared__ float rowsum[64];

    const int tid = threadIdx.x;
    const int i   = blockIdx.y >> 4;    // / KB_
    const int j   = blockIdx.y & 15;    // % KB_
    const int s0  = blockIdx.x * 64;

    // distance-weight table + key-mask row into smem
    {
        float ar = alpha_p[0];
        float alpha = ar > 0.f ? ar : 0.01f * ar;   // leaky_relu(slope 0.01)
        for (int d = tid; d < SEQ_; d += 256) dtab[d] = __expf(-alpha * (float)d);
        for (int t = tid; t < SEQ_; t += 256) km[t] = kmask[j * SEQ_ + t];
    }

    // GEMM thread mapping: 16x16 threads, 4x4 micro-tile
    const int ty = tid >> 4, tx = tid & 15;
    // staging-load mapping: each thread one float4
    const int arow = tid >> 2, acol4 = (tid & 3) * 4;
    // epilogue mapping: 4 threads per row, 16 cols each
    const int row = tid >> 2, q = tid & 3;
    const int s   = s0 + row;

    const float* qbase  = g_qn + ((long)i * SEQ_ + s0 + arow) * HID_;
    const float* kbase0 = g_kn + (long)j * SEQ_ * HID_;

    float m = NEG_BIG, l = 0.f, r = 0.f;   // online softmax state (replicated per quad)

    __syncthreads();   // dtab/km visible

    for (int t0 = 0; t0 < SEQ_; t0 += 64) {
        float acc[4][4];
        #pragma unroll
        for (int a = 0; a < 4; a++)
            #pragma unroll
            for (int b = 0; b < 4; b++) acc[a][b] = 0.f;

        const float* kbase = kbase0 + (long)(t0 + arow) * HID_;

        for (int k0 = 0; k0 < HID_; k0 += 16) {
            float4 qv = *(const float4*)(qbase + k0 + acol4);
            float4 kv = *(const float4*)(kbase + k0 + acol4);
            As[acol4 + 0][arow] = qv.x; As[acol4 + 1][arow] = qv.y;
            As[acol4 + 2][arow] = qv.z; As[acol4 + 3][arow] = qv.w;
            Bs[acol4 + 0][arow] = kv.x; Bs[acol4 + 1][arow] = kv.y;
            Bs[acol4 + 2][arow] = kv.z; Bs[acol4 + 3][arow] = kv.w;
            __syncthreads();
            #pragma unroll
            for (int kk = 0; kk < 16; kk++) {
                float4 a = *(const float4*)&As[kk][ty * 4];
                float4 b = *(const float4*)&Bs[kk][tx * 4];
                acc[0][0] += a.x * b.x; acc[0][1] += a.x * b.y;
                acc[0][2] += a.x * b.z; acc[0][3] += a.x * b.w;
                acc[1][0] += a.y * b.x; acc[1][1] += a.y * b.y;
                acc[1][2] += a.y * b.z; acc[1][3] += a.y * b.w;
                acc[2][0] += a.z * b.x; acc[2][1] += a.z * b.y;
                acc[2][2] += a.z * b.z; acc[2][3] += a.z * b.w;
                acc[3][0] += a.w * b.x; acc[3][1] += a.w * b.y;
                acc[3][2] += a.w * b.z; acc[3][3] += a.w * b.w;
            }
            __syncthreads();
        }

        // park C tile in smem, switch to row-major epilogue mapping
        #pragma unroll
        for (int rr = 0; rr < 4; rr++)
            *(float4*)&Cs[ty * 4 + rr][tx * 4] =
                make_float4(acc[rr][0], acc[rr][1], acc[rr][2], acc[rr][3]);
        __syncthreads();

        // ---- online softmax over this 64-col tile ----
        float cc[16], lg[16];
        float tmax = NEG_BIG;
        const int colbase = t0 + q * 16;
        #pragma unroll
        for (int e = 0; e < 16; e++) {
            float c = Cs[row][q * 16 + e];
            int t = colbase + e;
            float w = dtab[abs(s - t)];
            float lge = (km[t] != 0) ? c * w : NEG_BIG;
            cc[e] = c; lg[e] = lge;
            tmax = fmaxf(tmax, lge);
        }
        tmax = fmaxf(tmax, __shfl_xor_sync(0xffffffffu, tmax, 1));
        tmax = fmaxf(tmax, __shfl_xor_sync(0xffffffffu, tmax, 2));

        float newm = fmaxf(m, tmax);
        if (newm > -1e37f) {
            float scale = (m > -1e37f) ? __expf(m - newm) : 0.f;
            float tl = 0.f, tr = 0.f;
            #pragma unroll
            for (int e = 0; e < 16; e++) {
                if (lg[e] > -1e37f) {
                    float p = __expf(lg[e] - newm);
                    tl += p; tr += p * cc[e];
                }
            }
            tl += __shfl_xor_sync(0xffffffffu, tl, 1);
            tl += __shfl_xor_sync(0xffffffffu, tl, 2);
            tr += __shfl_xor_sync(0xffffffffu, tr, 1);
            tr += __shfl_xor_sync(0xffffffffu, tr, 2);
            l = l * scale + tl;
            r = r * scale + tr;
            m = newm;
        }
        __syncthreads();   // Cs reuse next tile
    }

    // finalize: score_row = (Σ p·c) = r/l ; zero if row fully masked; apply q_mask
    if (q == 0) {
        float val = (l > 0.f) ? (r / l) : 0.f;          // matches nan_to_num(softmax)=0
        if (qmask[i * SEQ_ + s] == 0) val = 0.f;
        rowsum[row] = val;
    }
    __syncthreads();

    if (tid < 64) {
        float v = rowsum[tid];
        #pragma unroll
        for (int o = 16; o; o >>= 1) v += __shfl_xor_sync(0xffffffffu, v, o);
        if ((tid & 31) == 0) rowsum[tid >> 5] = v;
    }
    __syncthreads();
    if (tid == 0)
        g_partial[blockIdx.y * STILES + blockIdx.x] = rowsum[0] + rowsum[1];
}

// ---------------- kernel 2: reduce s-tile partials -> out[B,KB] ----------------
__global__ void li_reduce(float* __restrict__ out) {
    int p = threadIdx.x;              // 0..127
    float sum = 0.f;
    #pragma unroll
    for (int b = 0; b < STILES; b++) sum += g_partial[p * STILES + b];
    out[p] = sum;
}

// ---------------- launch ----------------
extern "C" void kernel_launch(void* const* d_in, const int* in_sizes, int n_in,
                              void* d_out, int out_size) {
    const float* qe    = (const float*)d_in[0];   // [8,512,768]
    const float* ke    = (const float*)d_in[1];   // [16,512,768]
    const float* alpha = (const float*)d_in[2];   // scalar
    const int*   qm    = (const int*)d_in[3];     // [8,512]
    const int*   kmm   = (const int*)d_in[4];     // [16,512]
    float* out = (float*)d_out;                   // [8,16]

    norm_rows<<<B_ * SEQ_, 192>>>(qe, 0);
    norm_rows<<<KB_ * SEQ_, 192>>>(ke, 1);
    dim3 grid(STILES, NPAIR);
    li_main<<<grid, 256>>>(alpha, qm, kmm);
    li_reduce<<<1, NPAIR>>>(out);
}

// round 6
// speedup vs baseline: 8.5993x; 8.5993x over previous
#include <cuda_runtime.h>
#include <cuda_fp16.h>
#include <math.h>
#include <stdint.h>

#define B_    8
#define KB_   16
#define SEQ_  512
#define HID_  768
#define NPAIR 128
#define STILES 4                 // s-tiles of 128 rows
#define NEG_BIG (-3.0e38f)

// ---------------- scratch (static device arrays; no allocation) ----------------
__device__ __align__(256) __half g_qn[B_ * SEQ_ * HID_];   // 6.3 MB
__device__ __align__(256) __half g_kn[KB_ * SEQ_ * HID_];  // 12.6 MB
__device__ float g_partial[NPAIR * STILES];

// ---------------- helpers ----------------
__device__ __forceinline__ uint32_t smem_u32(const void* p) {
    uint32_t a;
    asm("{ .reg .u64 t; cvta.to.shared.u64 t, %1; cvt.u32.u64 %0, t; }" : "=r"(a) : "l"(p));
    return a;
}
#define SWZ(off) ((off) ^ (((off) >> 3) & 0x70))

__device__ __forceinline__ void cp16(uint32_t saddr, const void* g) {
    asm volatile("cp.async.cg.shared.global [%0], [%1], 16;" :: "r"(saddr), "l"(g));
}
#define CP_COMMIT() asm volatile("cp.async.commit_group;" ::: "memory")
#define CP_WAIT0()  asm volatile("cp.async.wait_group 0;" ::: "memory")

#define LDSM4(r0, r1, r2, r3, addr) \
    asm volatile("ldmatrix.sync.aligned.m8n8.x4.shared.b16 {%0,%1,%2,%3}, [%4];" \
        : "=r"(r0), "=r"(r1), "=r"(r2), "=r"(r3) : "r"(addr))

#define MMA16816(d, a, b) \
    asm volatile("mma.sync.aligned.m16n8k16.row.col.f32.f16.f16.f32 " \
        "{%0,%1,%2,%3}, {%4,%5,%6,%7}, {%8,%9}, {%0,%1,%2,%3};" \
        : "+f"((d)[0]), "+f"((d)[1]), "+f"((d)[2]), "+f"((d)[3]) \
        : "r"((a)[0]), "r"((a)[1]), "r"((a)[2]), "r"((a)[3]), \
          "r"((b)[0]), "r"((b)[1]))

// fast exp on FMA/ALU pipes (x <= 0); avoids the MUFU throughput wall.
__device__ __forceinline__ float fexp(float x) {
    float t = fmaxf(x * 1.4426950408889634f, -126.0f);  // log2(e), clamp (handles -inf)
    float z = t + 12582912.0f;                          // round-to-nearest int
    float fl = z - 12582912.0f;
    float f = t - fl;                                   // f in [-0.5, 0.5]
    int n = __float_as_int(z) - 0x4B400000;             // integer part
    float p = 1.3333558146e-3f;
    p = fmaf(p, f, 9.6181291056e-3f);
    p = fmaf(p, f, 5.5504108664e-2f);
    p = fmaf(p, f, 2.4022650696e-1f);
    p = fmaf(p, f, 6.9314718056e-1f);
    p = fmaf(p, f, 1.0f);
    return __int_as_float((n + 127) << 23) * p;
}

// ---------------- smem layout (dynamic) ----------------
#define OFF_DTAB  0                     // 512 floats
#define OFF_KM    2048                  // 512 ints
#define OFF_EPI   4096                  // m[256], l[256], r[256], rowv[128]
#define OFF_Q0    8192                  // 2 x 16KB Q stage
#define OFF_K0    40960                 // 2 x 16KB K stage
#define SMEM_TOTAL 73728

// ---------------- kernel 0: row L2 normalize -> fp16 ----------------
__global__ __launch_bounds__(192) void norm_rows(const float* __restrict__ in, int which) {
    __half* __restrict__ outb = which ? g_kn : g_qn;
    const long row = blockIdx.x;
    const float4* src = (const float4*)(in + row * (long)HID_);
    int t = threadIdx.x;

    float4 v = src[t];
    float s = v.x * v.x + v.y * v.y + v.z * v.z + v.w * v.w;
    #pragma unroll
    for (int o = 16; o; o >>= 1) s += __shfl_xor_sync(0xffffffffu, s, o);

    __shared__ float red[6];
    __shared__ float scale_sh;
    if ((t & 31) == 0) red[t >> 5] = s;
    __syncthreads();
    if (t == 0) {
        float tot = 0.f;
        #pragma unroll
        for (int w = 0; w < 6; w++) tot += red[w];
        scale_sh = 1.0f / fmaxf(sqrtf(tot), 1e-12f);
    }
    __syncthreads();
    float sc = scale_sh;
    __half2* dst = (__half2*)(outb + row * (long)HID_);
    dst[t * 2 + 0] = __floats2half2_rn(v.x * sc, v.y * sc);
    dst[t * 2 + 1] = __floats2half2_rn(v.z * sc, v.w * sc);
}

// ---------------- kernel 1: HMMA GEMM + fused online softmax ----------------
// grid = (STILES, NPAIR); 256 threads (8 warps), 2 CTAs/SM.
// Warp w: rows (w>>1)*32..+32 of the 128 s-rows, cols (w&1)*64..+64 of each 128 t-tile.
__global__ __launch_bounds__(256, 2) void li_main(const float* __restrict__ alpha_p,
                                                  const int*   __restrict__ qmask,
                                                  const int*   __restrict__ kmask) {
    extern __shared__ char sm[];
    const uint32_t sb = smem_u32(sm);
    const int tid = threadIdx.x, wid = tid >> 5, lane = tid & 31;
    const int wr = wid >> 1, wc = wid & 1;
    const int pair = blockIdx.y;
    const int i = pair >> 4, j = pair & 15;
    const int s0 = blockIdx.x * 128;

    float* dtab = (float*)(sm + OFF_DTAB);
    int*   km   = (int*)(sm + OFF_KM);
    float* epi  = (float*)(sm + OFF_EPI);

    {
        float ar = alpha_p[0];
        float alpha = ar > 0.f ? ar : 0.01f * ar;    // leaky_relu
        for (int d = tid; d < SEQ_; d += 256) dtab[d] = __expf(-alpha * (float)d);
        for (int t = tid; t < SEQ_; t += 256) km[t] = kmask[j * SEQ_ + t];
    }
    __syncthreads();

    const uint4* qsrc = (const uint4*)(g_qn + ((long)i * SEQ_ + s0) * HID_);
    const uint4* ksrc = (const uint4*)(g_kn + (long)j * SEQ_ * HID_);

    // per-lane online softmax state for 4 row-groups [mt][h]
    float m4[2][2], l4[2][2], r4[2][2];
    #pragma unroll
    for (int a = 0; a < 2; a++)
        #pragma unroll
        for (int b = 0; b < 2; b++) { m4[a][b] = NEG_BIG; l4[a][b] = 0.f; r4[a][b] = 0.f; }

    for (int tt = 0; tt < 4; tt++) {
        const int t0 = tt * 128;
        float acc[2][8][4];
        #pragma unroll
        for (int a = 0; a < 2; a++)
            #pragma unroll
            for (int b = 0; b < 8; b++)
                #pragma unroll
                for (int e = 0; e < 4; e++) acc[a][b][e] = 0.f;

        // stage chunk 0
        {
            uint32_t qb = sb + OFF_Q0, kb = sb + OFF_K0;
            #pragma unroll
            for (int it = 0; it < 4; it++) {
                int idx = tid + it * 256;
                int r = idx >> 3, seg = idx & 7;
                uint32_t so = SWZ((uint32_t)(r * 128 + seg * 16));
                cp16(qb + so, qsrc + r * 96 + seg);
                cp16(kb + so, ksrc + (t0 + r) * 96 + seg);
            }
            CP_COMMIT();
        }

        for (int kc = 0; kc < 12; kc++) {
            const int b = kc & 1;
            CP_WAIT0();
            __syncthreads();
            if (kc < 11) {     // prefetch next chunk into other buffer
                uint32_t qb = sb + OFF_Q0 + (b ^ 1) * 16384;
                uint32_t kb = sb + OFF_K0 + (b ^ 1) * 16384;
                #pragma unroll
                for (int it = 0; it < 4; it++) {
                    int idx = tid + it * 256;
                    int r = idx >> 3, seg = idx & 7;
                    uint32_t so = SWZ((uint32_t)(r * 128 + seg * 16));
                    cp16(qb + so, qsrc + r * 96 + (kc + 1) * 8 + seg);
                    cp16(kb + so, ksrc + (t0 + r) * 96 + (kc + 1) * 8 + seg);
                }
                CP_COMMIT();
            }
            // MMA on buffer b
            const uint32_t qbase = sb + OFF_Q0 + b * 16384;
            const uint32_t kbase = sb + OFF_K0 + b * 16384;
            #pragma unroll
            for (int ks = 0; ks < 4; ks++) {
                uint32_t afr[2][4];
                #pragma unroll
                for (int mt = 0; mt < 2; mt++) {
                    int rowA = wr * 32 + mt * 16 + (lane & 7) + ((lane >> 3) & 1) * 8;
                    int kcol = ks * 16 + (lane >> 4) * 8;
                    uint32_t ad = qbase + SWZ((uint32_t)(rowA * 128 + kcol * 2));
                    LDSM4(afr[mt][0], afr[mt][1], afr[mt][2], afr[mt][3], ad);
                }
                uint32_t bfr[8][2];
                #pragma unroll
                for (int np = 0; np < 4; np++) {
                    int nrow = wc * 64 + (np * 2 + (lane >> 4)) * 8 + (lane & 7);
                    int kcol = ks * 16 + ((lane >> 3) & 1) * 8;
                    uint32_t ad = kbase + SWZ((uint32_t)(nrow * 128 + kcol * 2));
                    LDSM4(bfr[np * 2][0], bfr[np * 2][1],
                          bfr[np * 2 + 1][0], bfr[np * 2 + 1][1], ad);
                }
                #pragma unroll
                for (int mt = 0; mt < 2; mt++)
                    #pragma unroll
                    for (int nt = 0; nt < 8; nt++)
                        MMA16816(acc[mt][nt], afr[mt], bfr[nt]);
            }
        }

        // ---- per-tile online softmax on register accumulators ----
        #pragma unroll
        for (int mt = 0; mt < 2; mt++) {
            #pragma unroll
            for (int h = 0; h < 2; h++) {
                int srow = s0 + wr * 32 + mt * 16 + h * 8 + (lane >> 2);
                float lg[16];
                float bm = NEG_BIG;
                #pragma unroll
                for (int nt = 0; nt < 8; nt++) {
                    #pragma unroll
                    for (int e = 0; e < 2; e++) {
                        int t = t0 + wc * 64 + nt * 8 + (lane & 3) * 2 + e;
                        float c = acc[mt][nt][h * 2 + e];
                        float w = dtab[abs(srow - t)];
                        float L = (km[t] != 0) ? c * w : NEG_BIG;
                        lg[nt * 2 + e] = L;
                        bm = fmaxf(bm, L);
                    }
                }
                float mv = m4[mt][h];
                float nm = fmaxf(mv, bm);
                if (nm > -1e37f) {
                    float scale = fexp(mv - nm);
                    float lv = l4[mt][h] * scale, rv = r4[mt][h] * scale;
                    #pragma unroll
                    for (int nt = 0; nt < 8; nt++) {
                        #pragma unroll
                        for (int e = 0; e < 2; e++) {
                            float p = fexp(lg[nt * 2 + e] - nm);
                            lv += p;
                            rv += p * acc[mt][nt][h * 2 + e];
                        }
                    }
                    m4[mt][h] = nm; l4[mt][h] = lv; r4[mt][h] = rv;
                }
            }
        }
    }

    // ---- final combine: quad -> smem -> halves -> rows -> partial ----
    float* mS = epi;          // [2][128]
    float* lS = epi + 256;
    float* rS = epi + 512;
    float* rowv = epi + 768;  // [128]

    #pragma unroll
    for (int mt = 0; mt < 2; mt++) {
        #pragma unroll
        for (int h = 0; h < 2; h++) {
            float mv = m4[mt][h], lv = l4[mt][h], rv = r4[mt][h];
            float mo = mv;
            mo = fmaxf(mo, __shfl_xor_sync(0xffffffffu, mo, 1));
            mo = fmaxf(mo, __shfl_xor_sync(0xffffffffu, mo, 2));
            float sc = (mo > -1e37f) ? fexp(mv - mo) : 0.f;
            float ls = lv * sc, rs = rv * sc;
            ls += __shfl_xor_sync(0xffffffffu, ls, 1);
            ls += __shfl_xor_sync(0xffffffffu, ls, 2);
            rs += __shfl_xor_sync(0xffffffffu, rs, 1);
            rs += __shfl_xor_sync(0xffffffffu, rs, 2);
            if ((lane & 3) == 0) {
                int row = wr * 32 + mt * 16 + h * 8 + (lane >> 2);
                mS[wc * 128 + row] = mo;
                lS[wc * 128 + row] = ls;
                rS[wc * 128 + row] = rs;
            }
        }
    }
    __syncthreads();

    if (tid < 128) {
        float m0 = mS[tid], m1 = mS[128 + tid];
        float mm = fmaxf(m0, m1);
        float ll = 0.f, rr = 0.f;
        if (mm > -1e37f) {
            float e0 = fexp(m0 - mm), e1 = fexp(m1 - mm);
            ll = lS[tid] * e0 + lS[128 + tid] * e1;
            rr = rS[tid] * e0 + rS[128 + tid] * e1;
        }
        float v = (ll > 0.f) ? rr / ll : 0.f;     // nan_to_num(softmax)=0 for dead rows
        if (qmask[i * SEQ_ + s0 + tid] == 0) v = 0.f;
        rowv[tid] = v;
    }
    __syncthreads();
    if (tid < 128) {
        float v = rowv[tid];
        #pragma unroll
        for (int o = 16; o; o >>= 1) v += __shfl_xor_sync(0xffffffffu, v, o);
        if (lane == 0) mS[wid] = v;
    }
    __syncthreads();
    if (tid == 0)
        g_partial[pair * STILES + blockIdx.x] = mS[0] + mS[1] + mS[2] + mS[3];
}

// ---------------- kernel 2: reduce s-tile partials -> out[B,KB] ----------------
__global__ void li_reduce(float* __restrict__ out) {
    int p = threadIdx.x;   // 0..127
    float sum = 0.f;
    #pragma unroll
    for (int b = 0; b < STILES; b++) sum += g_partial[p * STILES + b];
    out[p] = sum;
}

// ---------------- launch ----------------
extern "C" void kernel_launch(void* const* d_in, const int* in_sizes, int n_in,
                              void* d_out, int out_size) {
    const float* qe    = (const float*)d_in[0];   // [8,512,768]
    const float* ke    = (const float*)d_in[1];   // [16,512,768]
    const float* alpha = (const float*)d_in[2];   // scalar
    const int*   qm    = (const int*)d_in[3];     // [8,512]
    const int*   kmm   = (const int*)d_in[4];     // [16,512]
    float* out = (float*)d_out;                   // [8,16]

    cudaFuncSetAttribute(li_main, cudaFuncAttributeMaxDynamicSharedMemorySize, SMEM_TOTAL);

    norm_rows<<<B_ * SEQ_, 192>>>(qe, 0);
    norm_rows<<<KB_ * SEQ_, 192>>>(ke, 1);
    dim3 grid(STILES, NPAIR);
    li_main<<<grid, 256, SMEM_TOTAL>>>(alpha, qm, kmm);
    li_reduce<<<1, NPAIR>>>(out);
}

// round 7
// speedup vs baseline: 18.5831x; 2.1610x over previous
#include <cuda_runtime.h>
#include <cuda_fp16.h>
#include <math.h>
#include <stdint.h>

#define B_    8
#define KB_   16
#define SEQ_  512
#define HID_  768
#define NPAIR 128
#define STILES 4                 // max s-tiles of 128 rows
#define NEG_BIG (-3.0e38f)

// ---------------- scratch (static device arrays; no allocation) ----------------
__device__ __align__(256) __half g_qn[B_ * SEQ_ * HID_];   // compacted normalized queries
__device__ __align__(256) __half g_kn[KB_ * SEQ_ * HID_];  // compacted normalized keys
__device__ float g_partial[NPAIR * STILES];
__device__ int g_qidx[B_ * SEQ_];
__device__ int g_kidx[KB_ * SEQ_];
__device__ int g_qcnt[B_];
__device__ int g_kcnt[KB_];

// ---------------- helpers ----------------
__device__ __forceinline__ uint32_t smem_u32(const void* p) {
    uint32_t a;
    asm("{ .reg .u64 t; cvta.to.shared.u64 t, %1; cvt.u32.u64 %0, t; }" : "=r"(a) : "l"(p));
    return a;
}
#define SWZ(off) ((off) ^ (((off) >> 3) & 0x70))

__device__ __forceinline__ void cp16(uint32_t saddr, const void* g) {
    asm volatile("cp.async.cg.shared.global [%0], [%1], 16;" :: "r"(saddr), "l"(g));
}
#define CP_COMMIT() asm volatile("cp.async.commit_group;" ::: "memory")
#define CP_WAIT0()  asm volatile("cp.async.wait_group 0;" ::: "memory")

#define LDSM4(r0, r1, r2, r3, addr) \
    asm volatile("ldmatrix.sync.aligned.m8n8.x4.shared.b16 {%0,%1,%2,%3}, [%4];" \
        : "=r"(r0), "=r"(r1), "=r"(r2), "=r"(r3) : "r"(addr))

#define MMA16816(d, a, b) \
    asm volatile("mma.sync.aligned.m16n8k16.row.col.f32.f16.f16.f32 " \
        "{%0,%1,%2,%3}, {%4,%5,%6,%7}, {%8,%9}, {%0,%1,%2,%3};" \
        : "+f"((d)[0]), "+f"((d)[1]), "+f"((d)[2]), "+f"((d)[3]) \
        : "r"((a)[0]), "r"((a)[1]), "r"((a)[2]), "r"((a)[3]), \
          "r"((b)[0]), "r"((b)[1]))

// fast exp on FMA/ALU pipes (x <= 0); avoids the MUFU throughput wall.
__device__ __forceinline__ float fexp(float x) {
    float t = fmaxf(x * 1.4426950408889634f, -126.0f);
    float z = t + 12582912.0f;
    float fl = z - 12582912.0f;
    float f = t - fl;
    int n = __float_as_int(z) - 0x4B400000;
    float p = 1.3333558146e-3f;
    p = fmaf(p, f, 9.6181291056e-3f);
    p = fmaf(p, f, 5.5504108664e-2f);
    p = fmaf(p, f, 2.4022650696e-1f);
    p = fmaf(p, f, 6.9314718056e-1f);
    p = fmaf(p, f, 1.0f);
    return __int_as_float((n + 127) << 23) * p;
}

// ---------------- smem layout (dynamic) ----------------
#define OFF_DTAB  0                     // 512 floats
#define OFF_QIDX  2048                  // 128 ints
#define OFF_KIDX  2560                  // 128 ints
#define OFF_EPI   3072                  // m[256], l[256], r[256], rowv[128] = 3584B
#define OFF_Q0    8192                  // 2 x 16KB Q stage
#define OFF_K0    40960                 // 2 x 16KB K stage
#define SMEM_TOTAL 73728

// ---------------- kernel A: compact valid indices per batch row ----------------
// 24 blocks x 32 threads: blocks 0..7 = q lists, 8..23 = k lists.
__global__ void compact_masks(const int* __restrict__ qm, const int* __restrict__ kmm) {
    int lid = threadIdx.x;
    int which = blockIdx.x;
    const int* src; int* dst; int* cnt;
    if (which < 8) { src = qm + which * SEQ_;        dst = g_qidx + which * SEQ_;        cnt = g_qcnt + which; }
    else           { src = kmm + (which - 8) * SEQ_; dst = g_kidx + (which - 8) * SEQ_;  cnt = g_kcnt + (which - 8); }
    int base = 0;
    for (int c = 0; c < SEQ_; c += 32) {
        int v = src[c + lid] != 0;
        unsigned b = __ballot_sync(0xffffffffu, v);
        int off = __popc(b & ((1u << lid) - 1));
        if (v) dst[base + off] = c + lid;
        base += __popc(b);
    }
    if (lid == 0) *cnt = base;
}

// ---------------- kernel 0: L2 normalize valid rows -> fp16, compacted order ----
__global__ __launch_bounds__(192) void norm_rows(const float* __restrict__ in, int which) {
    const int nb = blockIdx.x;
    const int i  = nb >> 9;             // batch row
    const int sp = nb & 511;            // compacted slot
    const int cnt = which ? g_kcnt[i] : g_qcnt[i];
    if (sp >= cnt) return;
    const int orig = (which ? g_kidx : g_qidx)[i * SEQ_ + sp];

    const float4* src = (const float4*)(in + ((long)i * SEQ_ + orig) * HID_);
    __half* outb = (which ? g_kn : g_qn) + ((long)i * SEQ_ + sp) * HID_;
    int t = threadIdx.x;

    float4 v = src[t];
    float s = v.x * v.x + v.y * v.y + v.z * v.z + v.w * v.w;
    #pragma unroll
    for (int o = 16; o; o >>= 1) s += __shfl_xor_sync(0xffffffffu, s, o);

    __shared__ float red[6];
    __shared__ float scale_sh;
    if ((t & 31) == 0) red[t >> 5] = s;
    __syncthreads();
    if (t == 0) {
        float tot = 0.f;
        #pragma unroll
        for (int w = 0; w < 6; w++) tot += red[w];
        scale_sh = 1.0f / fmaxf(sqrtf(tot), 1e-12f);
    }
    __syncthreads();
    float sc = scale_sh;
    __half2* dst = (__half2*)outb;
    dst[t * 2 + 0] = __floats2half2_rn(v.x * sc, v.y * sc);
    dst[t * 2 + 1] = __floats2half2_rn(v.z * sc, v.w * sc);
}

// ---------------- kernel 1: HMMA GEMM + fused online softmax (compacted dims) ----
__global__ __launch_bounds__(256, 2) void li_main(const float* __restrict__ alpha_p) {
    extern __shared__ char sm[];
    const uint32_t sb = smem_u32(sm);
    const int tid = threadIdx.x, wid = tid >> 5, lane = tid & 31;
    const int wr = wid >> 1, wc = wid & 1;
    const int pair = blockIdx.y;
    const int i = pair >> 4, j = pair & 15;
    const int s0 = blockIdx.x * 128;

    const int qcnt = g_qcnt[i];
    const int kcnt = g_kcnt[j];
    if (s0 >= qcnt || kcnt == 0) {
        if (tid == 0) g_partial[pair * STILES + blockIdx.x] = 0.f;
        return;
    }
    const int ktiles = (kcnt + 127) >> 7;

    float* dtab  = (float*)(sm + OFF_DTAB);
    int*   qidxS = (int*)(sm + OFF_QIDX);
    int*   kidxS = (int*)(sm + OFF_KIDX);
    float* epi   = (float*)(sm + OFF_EPI);

    {
        float ar = alpha_p[0];
        float alpha = ar > 0.f ? ar : 0.01f * ar;    // leaky_relu
        for (int d = tid; d < SEQ_; d += 256) dtab[d] = __expf(-alpha * (float)d);
        if (tid < 128) qidxS[tid] = g_qidx[i * SEQ_ + min(s0 + tid, qcnt - 1)];
    }

    // contiguous compacted rows, clamped to last valid (keeps values finite)
    int qr[4];
    #pragma unroll
    for (int it = 0; it < 4; it++)
        qr[it] = min(s0 + ((tid + it * 256) >> 3), qcnt - 1);
    const int seg = tid & 7;

    const uint4* qsrc = (const uint4*)g_qn + (long)i * SEQ_ * 96;
    const uint4* ksrc = (const uint4*)g_kn + (long)j * SEQ_ * 96;

    float m4[2][2], l4[2][2], r4[2][2];
    #pragma unroll
    for (int a = 0; a < 2; a++)
        #pragma unroll
        for (int b = 0; b < 2; b++) { m4[a][b] = NEG_BIG; l4[a][b] = 0.f; r4[a][b] = 0.f; }

    __syncthreads();   // dtab/qidxS visible

    for (int tt = 0; tt < ktiles; tt++) {
        const int t0 = tt * 128;
        int kr[4];
        #pragma unroll
        for (int it = 0; it < 4; it++)
            kr[it] = min(t0 + ((tid + it * 256) >> 3), kcnt - 1);

        if (tid < 128) kidxS[tid] = g_kidx[j * SEQ_ + min(t0 + tid, kcnt - 1)];
        __syncthreads();   // kidxS stable; prior epilogue reads done

        float acc[2][8][4];
        #pragma unroll
        for (int a = 0; a < 2; a++)
            #pragma unroll
            for (int b = 0; b < 8; b++)
                #pragma unroll
                for (int e = 0; e < 4; e++) acc[a][b][e] = 0.f;

        // stage chunk 0
        {
            uint32_t qb = sb + OFF_Q0, kb = sb + OFF_K0;
            #pragma unroll
            for (int it = 0; it < 4; it++) {
                int r = (tid + it * 256) >> 3;
                uint32_t so = SWZ((uint32_t)(r * 128 + seg * 16));
                cp16(qb + so, qsrc + qr[it] * 96 + seg);
                cp16(kb + so, ksrc + kr[it] * 96 + seg);
            }
            CP_COMMIT();
        }

        for (int kc = 0; kc < 12; kc++) {
            const int b = kc & 1;
            CP_WAIT0();
            __syncthreads();
            if (kc < 11) {
                uint32_t qb = sb + OFF_Q0 + (b ^ 1) * 16384;
                uint32_t kb = sb + OFF_K0 + (b ^ 1) * 16384;
                #pragma unroll
                for (int it = 0; it < 4; it++) {
                    int r = (tid + it * 256) >> 3;
                    uint32_t so = SWZ((uint32_t)(r * 128 + seg * 16));
                    cp16(qb + so, qsrc + qr[it] * 96 + (kc + 1) * 8 + seg);
                    cp16(kb + so, ksrc + kr[it] * 96 + (kc + 1) * 8 + seg);
                }
                CP_COMMIT();
            }
            const uint32_t qbase = sb + OFF_Q0 + b * 16384;
            const uint32_t kbase = sb + OFF_K0 + b * 16384;
            #pragma unroll
            for (int ks = 0; ks < 4; ks++) {
                uint32_t afr[2][4];
                #pragma unroll
                for (int mt = 0; mt < 2; mt++) {
                    int rowA = wr * 32 + mt * 16 + (lane & 7) + ((lane >> 3) & 1) * 8;
                    int kcol = ks * 16 + (lane >> 4) * 8;
                    uint32_t ad = qbase + SWZ((uint32_t)(rowA * 128 + kcol * 2));
                    LDSM4(afr[mt][0], afr[mt][1], afr[mt][2], afr[mt][3], ad);
                }
                uint32_t bfr[8][2];
                #pragma unroll
                for (int np = 0; np < 4; np++) {
                    int nrow = wc * 64 + (np * 2 + (lane >> 4)) * 8 + (lane & 7);
                    int kcol = ks * 16 + ((lane >> 3) & 1) * 8;
                    uint32_t ad = kbase + SWZ((uint32_t)(nrow * 128 + kcol * 2));
                    LDSM4(bfr[np * 2][0], bfr[np * 2][1],
                          bfr[np * 2 + 1][0], bfr[np * 2 + 1][1], ad);
                }
                #pragma unroll
                for (int mt = 0; mt < 2; mt++)
                    #pragma unroll
                    for (int nt = 0; nt < 8; nt++)
                        MMA16816(acc[mt][nt], afr[mt], bfr[nt]);
            }
        }

        // ---- per-tile online softmax on register accumulators ----
        #pragma unroll
        for (int mt = 0; mt < 2; mt++) {
            #pragma unroll
            for (int h = 0; h < 2; h++) {
                int rowl = wr * 32 + mt * 16 + h * 8 + (lane >> 2);
                int sO = qidxS[rowl];
                float lg[16];
                float bm = NEG_BIG;
                #pragma unroll
                for (int nt = 0; nt < 8; nt++) {
                    #pragma unroll
                    for (int e = 0; e < 2; e++) {
                        int tl = wc * 64 + nt * 8 + (lane & 3) * 2 + e;
                        float c = acc[mt][nt][h * 2 + e];
                        float w = dtab[abs(sO - kidxS[tl])];
                        float L = (t0 + tl < kcnt) ? c * w : NEG_BIG;
                        lg[nt * 2 + e] = L;
                        bm = fmaxf(bm, L);
                    }
                }
                float mv = m4[mt][h];
                float nm = fmaxf(mv, bm);
                if (nm > -1e37f) {
                    float scale = fexp(mv - nm);
                    float lv = l4[mt][h] * scale, rv = r4[mt][h] * scale;
                    #pragma unroll
                    for (int nt = 0; nt < 8; nt++) {
                        #pragma unroll
                        for (int e = 0; e < 2; e++) {
                            float p = fexp(lg[nt * 2 + e] - nm);
                            lv += p;
                            rv += p * acc[mt][nt][h * 2 + e];
                        }
                    }
                    m4[mt][h] = nm; l4[mt][h] = lv; r4[mt][h] = rv;
                }
            }
        }
        __syncthreads();   // epilogue reads of kidxS done before next tile rewrites
    }

    // ---- final combine: quad -> smem -> halves -> rows -> partial ----
    float* mS = epi;          // [2][128]
    float* lS = epi + 256;
    float* rS = epi + 512;
    float* rowv = epi + 768;  // [128]

    #pragma unroll
    for (int mt = 0; mt < 2; mt++) {
        #pragma unroll
        for (int h = 0; h < 2; h++) {
            float mv = m4[mt][h], lv = l4[mt][h], rv = r4[mt][h];
            float mo = mv;
            mo = fmaxf(mo, __shfl_xor_sync(0xffffffffu, mo, 1));
            mo = fmaxf(mo, __shfl_xor_sync(0xffffffffu, mo, 2));
            float sc = (mo > -1e37f) ? fexp(mv - mo) : 0.f;
            float ls = lv * sc, rs = rv * sc;
            ls += __shfl_xor_sync(0xffffffffu, ls, 1);
            ls += __shfl_xor_sync(0xffffffffu, ls, 2);
            rs += __shfl_xor_sync(0xffffffffu, rs, 1);
            rs += __shfl_xor_sync(0xffffffffu, rs, 2);
            if ((lane & 3) == 0) {
                int row = wr * 32 + mt * 16 + h * 8 + (lane >> 2);
                mS[wc * 128 + row] = mo;
                lS[wc * 128 + row] = ls;
                rS[wc * 128 + row] = rs;
            }
        }
    }
    __syncthreads();

    if (tid < 128) {
        float m0 = mS[tid], m1 = mS[128 + tid];
        float mm = fmaxf(m0, m1);
        float ll = 0.f, rr = 0.f;
        if (mm > -1e37f) {
            float e0 = fexp(m0 - mm), e1 = fexp(m1 - mm);
            ll = lS[tid] * e0 + lS[128 + tid] * e1;
            rr = rS[tid] * e0 + rS[128 + tid] * e1;
        }
        float v = (ll > 0.f) ? rr / ll : 0.f;
        if (s0 + tid >= qcnt) v = 0.f;        // clamped duplicate rows dropped
        rowv[tid] = v;
    }
    __syncthreads();
    if (tid < 128) {
        float v = rowv[tid];
        #pragma unroll
        for (int o = 16; o; o >>= 1) v += __shfl_xor_sync(0xffffffffu, v, o);
        if (lane == 0) mS[wid] = v;
    }
    __syncthreads();
    if (tid == 0)
        g_partial[pair * STILES + blockIdx.x] = mS[0] + mS[1] + mS[2] + mS[3];
}

// ---------------- kernel 2: reduce s-tile partials -> out[B,KB] ----------------
__global__ void li_reduce(float* __restrict__ out) {
    int p = threadIdx.x;   // 0..127
    float sum = 0.f;
    #pragma unroll
    for (int b = 0; b < STILES; b++) sum += g_partial[p * STILES + b];
    out[p] = sum;
}

// ---------------- launch ----------------
extern "C" void kernel_launch(void* const* d_in, const int* in_sizes, int n_in,
                              void* d_out, int out_size) {
    const float* qe    = (const float*)d_in[0];   // [8,512,768]
    const float* ke    = (const float*)d_in[1];   // [16,512,768]
    const float* alpha = (const float*)d_in[2];   // scalar
    const int*   qm    = (const int*)d_in[3];     // [8,512]
    const int*   kmm   = (const int*)d_in[4];     // [16,512]
    float* out = (float*)d_out;                   // [8,16]

    cudaFuncSetAttribute(li_main, cudaFuncAttributeMaxDynamicSharedMemorySize, SMEM_TOTAL);

    compact_masks<<<24, 32>>>(qm, kmm);
    norm_rows<<<B_ * SEQ_, 192>>>(qe, 0);
    norm_rows<<<KB_ * SEQ_, 192>>>(ke, 1);
    dim3 grid(STILES, NPAIR);
    li_main<<<grid, 256, SMEM_TOTAL>>>(alpha);
    li_reduce<<<1, NPAIR>>>(out);
}

// round 8
// speedup vs baseline: 19.7470x; 1.0626x over previous
#include <cuda_runtime.h>
#include <cuda_fp16.h>
#include <math.h>
#include <stdint.h>

#define B_    8
#define KB_   16
#define SEQ_  512
#define HID_  768
#define NPAIR 128
#define STILES 4                 // max 128-row s-tiles
#define KTILES 4                 // max 128-col k-tiles
#define NEG_BIG (-3.0e38f)

// ---------------- scratch (static device arrays; no allocation) ----------------
__device__ __align__(256) __half g_qn[B_ * SEQ_ * HID_];   // compacted normalized queries
__device__ __align__(256) __half g_kn[KB_ * SEQ_ * HID_];  // compacted normalized keys
__device__ int g_qidx[B_ * SEQ_];
__device__ int g_kidx[KB_ * SEQ_];
__device__ int g_qcnt[B_];
__device__ int g_kcnt[KB_];
// per (pair, stile, ktile, row) softmax partials
#define MLR_N (NPAIR * STILES * KTILES * 128)
__device__ float g_m[MLR_N];
__device__ float g_l[MLR_N];
__device__ float g_r[MLR_N];

// ---------------- helpers ----------------
__device__ __forceinline__ uint32_t smem_u32(const void* p) {
    uint32_t a;
    asm("{ .reg .u64 t; cvta.to.shared.u64 t, %1; cvt.u32.u64 %0, t; }" : "=r"(a) : "l"(p));
    return a;
}
#define SWZ(off) ((off) ^ (((off) >> 3) & 0x70))

__device__ __forceinline__ void cp16(uint32_t saddr, const void* g) {
    asm volatile("cp.async.cg.shared.global [%0], [%1], 16;" :: "r"(saddr), "l"(g));
}
#define CP_COMMIT() asm volatile("cp.async.commit_group;" ::: "memory")
#define CP_WAIT0()  asm volatile("cp.async.wait_group 0;" ::: "memory")

#define LDSM4(r0, r1, r2, r3, addr) \
    asm volatile("ldmatrix.sync.aligned.m8n8.x4.shared.b16 {%0,%1,%2,%3}, [%4];" \
        : "=r"(r0), "=r"(r1), "=r"(r2), "=r"(r3) : "r"(addr))

#define MMA16816(d, a, b) \
    asm volatile("mma.sync.aligned.m16n8k16.row.col.f32.f16.f16.f32 " \
        "{%0,%1,%2,%3}, {%4,%5,%6,%7}, {%8,%9}, {%0,%1,%2,%3};" \
        : "+f"((d)[0]), "+f"((d)[1]), "+f"((d)[2]), "+f"((d)[3]) \
        : "r"((a)[0]), "r"((a)[1]), "r"((a)[2]), "r"((a)[3]), \
          "r"((b)[0]), "r"((b)[1]))

// fast exp on FMA/ALU pipes (x <= 0); avoids the MUFU throughput wall.
__device__ __forceinline__ float fexp(float x) {
    float t = fmaxf(x * 1.4426950408889634f, -126.0f);
    float z = t + 12582912.0f;
    float fl = z - 12582912.0f;
    float f = t - fl;
    int n = __float_as_int(z) - 0x4B400000;
    float p = 1.3333558146e-3f;
    p = fmaf(p, f, 9.6181291056e-3f);
    p = fmaf(p, f, 5.5504108664e-2f);
    p = fmaf(p, f, 2.4022650696e-1f);
    p = fmaf(p, f, 6.9314718056e-1f);
    p = fmaf(p, f, 1.0f);
    return __int_as_float((n + 127) << 23) * p;
}

// ---------------- smem layout (dynamic) ----------------
#define OFF_DTAB  0                     // 512 floats
#define OFF_QIDX  2048                  // 128 ints
#define OFF_KIDX  2560                  // 128 ints
#define OFF_EPI   3072                  // m[256], l[256], r[256]
#define OFF_Q0    8192                  // 2 x 16KB Q stage
#define OFF_K0    40960                 // 2 x 16KB K stage
#define SMEM_TOTAL 73728

// ---------------- kernel A: compact valid indices per batch row ----------------
__global__ void compact_masks(const int* __restrict__ qm, const int* __restrict__ kmm) {
    int lid = threadIdx.x;
    int which = blockIdx.x;
    const int* src; int* dst; int* cnt;
    if (which < 8) { src = qm + which * SEQ_;        dst = g_qidx + which * SEQ_;        cnt = g_qcnt + which; }
    else           { src = kmm + (which - 8) * SEQ_; dst = g_kidx + (which - 8) * SEQ_;  cnt = g_kcnt + (which - 8); }
    int base = 0;
    for (int c = 0; c < SEQ_; c += 32) {
        int v = src[c + lid] != 0;
        unsigned b = __ballot_sync(0xffffffffu, v);
        int off = __popc(b & ((1u << lid) - 1));
        if (v) dst[base + off] = c + lid;
        base += __popc(b);
    }
    if (lid == 0) *cnt = base;
}

// ---------------- kernel 0: L2 normalize valid rows -> fp16, compacted order ----
__global__ __launch_bounds__(192) void norm_rows(const float* __restrict__ in, int which) {
    const int nb = blockIdx.x;
    const int i  = nb >> 9;
    const int sp = nb & 511;
    const int cnt = which ? g_kcnt[i] : g_qcnt[i];
    if (sp >= cnt) return;
    const int orig = (which ? g_kidx : g_qidx)[i * SEQ_ + sp];

    const float4* src = (const float4*)(in + ((long)i * SEQ_ + orig) * HID_);
    __half* outb = (which ? g_kn : g_qn) + ((long)i * SEQ_ + sp) * HID_;
    int t = threadIdx.x;

    float4 v = src[t];
    float s = v.x * v.x + v.y * v.y + v.z * v.z + v.w * v.w;
    #pragma unroll
    for (int o = 16; o; o >>= 1) s += __shfl_xor_sync(0xffffffffu, s, o);

    __shared__ float red[6];
    __shared__ float scale_sh;
    if ((t & 31) == 0) red[t >> 5] = s;
    __syncthreads();
    if (t == 0) {
        float tot = 0.f;
        #pragma unroll
        for (int w = 0; w < 6; w++) tot += red[w];
        scale_sh = 1.0f / fmaxf(sqrtf(tot), 1e-12f);
    }
    __syncthreads();
    float sc = scale_sh;
    __half2* dst = (__half2*)outb;
    dst[t * 2 + 0] = __floats2half2_rn(v.x * sc, v.y * sc);
    dst[t * 2 + 1] = __floats2half2_rn(v.z * sc, v.w * sc);
}

// ---------------- kernel 1: one (pair, stile, ktile) tile per CTA ----------------
// grid = (KTILES, STILES, NPAIR); uniform unit work -> clean dynamic packing.
__global__ __launch_bounds__(256, 2) void li_tile(const float* __restrict__ alpha_p) {
    extern __shared__ char sm[];
    const uint32_t sb = smem_u32(sm);
    const int tid = threadIdx.x, wid = tid >> 5, lane = tid & 31;
    const int wr = wid >> 1, wc = wid & 1;
    const int pair = blockIdx.z;
    const int i = pair >> 4, j = pair & 15;
    const int s0 = blockIdx.y * 128;
    const int t0 = blockIdx.x * 128;

    const int qcnt = g_qcnt[i];
    const int kcnt = g_kcnt[j];
    if (s0 >= qcnt || t0 >= kcnt) return;    // dead tile: combine skips it

    float* dtab  = (float*)(sm + OFF_DTAB);
    int*   qidxS = (int*)(sm + OFF_QIDX);
    int*   kidxS = (int*)(sm + OFF_KIDX);
    float* epi   = (float*)(sm + OFF_EPI);

    {
        float ar = alpha_p[0];
        float alpha = ar > 0.f ? ar : 0.01f * ar;    // leaky_relu
        for (int d = tid; d < SEQ_; d += 256) dtab[d] = __expf(-alpha * (float)d);
        if (tid < 128) {
            qidxS[tid] = g_qidx[i * SEQ_ + min(s0 + tid, qcnt - 1)];
            kidxS[tid] = g_kidx[j * SEQ_ + min(t0 + tid, kcnt - 1)];
        }
    }

    int qr[4], kr[4];
    #pragma unroll
    for (int it = 0; it < 4; it++) {
        int r = (tid + it * 256) >> 3;
        qr[it] = min(s0 + r, qcnt - 1);
        kr[it] = min(t0 + r, kcnt - 1);
    }
    const int seg = tid & 7;

    const uint4* qsrc = (const uint4*)g_qn + (long)i * SEQ_ * 96;
    const uint4* ksrc = (const uint4*)g_kn + (long)j * SEQ_ * 96;

    float acc[2][8][4];
    #pragma unroll
    for (int a = 0; a < 2; a++)
        #pragma unroll
        for (int b = 0; b < 8; b++)
            #pragma unroll
            for (int e = 0; e < 4; e++) acc[a][b][e] = 0.f;

    // stage chunk 0
    {
        uint32_t qb = sb + OFF_Q0, kb = sb + OFF_K0;
        #pragma unroll
        for (int it = 0; it < 4; it++) {
            int r = (tid + it * 256) >> 3;
            uint32_t so = SWZ((uint32_t)(r * 128 + seg * 16));
            cp16(qb + so, qsrc + qr[it] * 96 + seg);
            cp16(kb + so, ksrc + kr[it] * 96 + seg);
        }
        CP_COMMIT();
    }
    __syncthreads();   // dtab/qidxS/kidxS visible

    for (int kc = 0; kc < 12; kc++) {
        const int b = kc & 1;
        CP_WAIT0();
        __syncthreads();
        if (kc < 11) {
            uint32_t qb = sb + OFF_Q0 + (b ^ 1) * 16384;
            uint32_t kb = sb + OFF_K0 + (b ^ 1) * 16384;
            #pragma unroll
            for (int it = 0; it < 4; it++) {
                int r = (tid + it * 256) >> 3;
                uint32_t so = SWZ((uint32_t)(r * 128 + seg * 16));
                cp16(qb + so, qsrc + qr[it] * 96 + (kc + 1) * 8 + seg);
                cp16(kb + so, ksrc + kr[it] * 96 + (kc + 1) * 8 + seg);
            }
            CP_COMMIT();
        }
        const uint32_t qbase = sb + OFF_Q0 + b * 16384;
        const uint32_t kbase = sb + OFF_K0 + b * 16384;
        #pragma unroll
        for (int ks = 0; ks < 4; ks++) {
            uint32_t afr[2][4];
            #pragma unroll
            for (int mt = 0; mt < 2; mt++) {
                int rowA = wr * 32 + mt * 16 + (lane & 7) + ((lane >> 3) & 1) * 8;
                int kcol = ks * 16 + (lane >> 4) * 8;
                uint32_t ad = qbase + SWZ((uint32_t)(rowA * 128 + kcol * 2));
                LDSM4(afr[mt][0], afr[mt][1], afr[mt][2], afr[mt][3], ad);
            }
            uint32_t bfr[8][2];
            #pragma unroll
            for (int np = 0; np < 4; np++) {
                int nrow = wc * 64 + (np * 2 + (lane >> 4)) * 8 + (lane & 7);
                int kcol = ks * 16 + ((lane >> 3) & 1) * 8;
                uint32_t ad = kbase + SWZ((uint32_t)(nrow * 128 + kcol * 2));
                LDSM4(bfr[np * 2][0], bfr[np * 2][1],
                      bfr[np * 2 + 1][0], bfr[np * 2 + 1][1], ad);
            }
            #pragma unroll
            for (int mt = 0; mt < 2; mt++)
                #pragma unroll
                for (int nt = 0; nt < 8; nt++)
                    MMA16816(acc[mt][nt], afr[mt], bfr[nt]);
        }
    }

    // ---- per-tile softmax partials (single pass, no online merge needed) ----
    float* mS = epi;          // [2][128]
    float* lS = epi + 256;
    float* rS = epi + 512;

    #pragma unroll
    for (int mt = 0; mt < 2; mt++) {
        #pragma unroll
        for (int h = 0; h < 2; h++) {
            int rowl = wr * 32 + mt * 16 + h * 8 + (lane >> 2);
            int sO = qidxS[rowl];
            float lg[16];
            float bm = NEG_BIG;
            #pragma unroll
            for (int nt = 0; nt < 8; nt++) {
                #pragma unroll
                for (int e = 0; e < 2; e++) {
                    int tl = wc * 64 + nt * 8 + (lane & 3) * 2 + e;
                    float c = acc[mt][nt][h * 2 + e];
                    float w = dtab[abs(sO - kidxS[tl])];
                    float L = (t0 + tl < kcnt) ? c * w : NEG_BIG;
                    lg[nt * 2 + e] = L;
                    bm = fmaxf(bm, L);
                }
            }
            // quad max (4 lanes own one row)
            bm = fmaxf(bm, __shfl_xor_sync(0xffffffffu, bm, 1));
            bm = fmaxf(bm, __shfl_xor_sync(0xffffffffu, bm, 2));
            float lv = 0.f, rv = 0.f;
            #pragma unroll
            for (int nt = 0; nt < 8; nt++) {
                #pragma unroll
                for (int e = 0; e < 2; e++) {
                    float p = fexp(lg[nt * 2 + e] - bm);
                    lv += p;
                    rv += p * acc[mt][nt][h * 2 + e];
                }
            }
            lv += __shfl_xor_sync(0xffffffffu, lv, 1);
            lv += __shfl_xor_sync(0xffffffffu, lv, 2);
            rv += __shfl_xor_sync(0xffffffffu, rv, 1);
            rv += __shfl_xor_sync(0xffffffffu, rv, 2);
            if ((lane & 3) == 0) {
                mS[wc * 128 + rowl] = bm;
                lS[wc * 128 + rowl] = lv;
                rS[wc * 128 + rowl] = rv;
            }
        }
    }
    __syncthreads();

    // cross-half merge + write per-row partials to gmem
    if (tid < 128) {
        float m0 = mS[tid], m1 = mS[128 + tid];
        float mm = fmaxf(m0, m1);
        float e0 = fexp(m0 - mm), e1 = fexp(m1 - mm);
        float ll = lS[tid] * e0 + lS[128 + tid] * e1;
        float rr = rS[tid] * e0 + rS[128 + tid] * e1;
        long o = ((((long)pair * STILES + blockIdx.y) * KTILES + blockIdx.x) << 7) + tid;
        g_m[o] = mm; g_l[o] = ll; g_r[o] = rr;
    }
}

// ---------------- kernel 2: merge ktile partials, row-sum -> out[B,KB] ----------
__global__ __launch_bounds__(128) void li_combine(float* __restrict__ out) {
    const int pair = blockIdx.x;
    const int i = pair >> 4, j = pair & 15;
    const int qcnt = g_qcnt[i], kcnt = g_kcnt[j];
    const int qtiles = (qcnt + 127) >> 7;
    const int ktiles = (kcnt + 127) >> 7;
    const int tid = threadIdx.x, lane = tid & 31;

    float sum = 0.f;
    for (int st = 0; st < qtiles; st++) {
        if (st * 128 + tid < qcnt) {
            long base = ((((long)pair * STILES + st) * KTILES) << 7) + tid;
            float m = NEG_BIG, l = 0.f, r = 0.f;
            for (int kt = 0; kt < ktiles; kt++) {
                long o = base + ((long)kt << 7);
                float m2 = g_m[o], l2 = g_l[o], r2 = g_r[o];
                float nm = fmaxf(m, m2);
                float e1 = fexp(m - nm), e2 = fexp(m2 - nm);
                l = l * e1 + l2 * e2;
                r = r * e1 + r2 * e2;
                m = nm;
            }
            sum += (l > 0.f) ? r / l : 0.f;
        }
    }
    #pragma unroll
    for (int o = 16; o; o >>= 1) sum += __shfl_xor_sync(0xffffffffu, sum, o);
    __shared__ float w4[4];
    if (lane == 0) w4[tid >> 5] = sum;
    __syncthreads();
    if (tid == 0) out[pair] = w4[0] + w4[1] + w4[2] + w4[3];
}

// ---------------- launch ----------------
extern "C" void kernel_launch(void* const* d_in, const int* in_sizes, int n_in,
                              void* d_out, int out_size) {
    const float* qe    = (const float*)d_in[0];   // [8,512,768]
    const float* ke    = (const float*)d_in[1];   // [16,512,768]
    const float* alpha = (const float*)d_in[2];   // scalar
    const int*   qm    = (const int*)d_in[3];     // [8,512]
    const int*   kmm   = (const int*)d_in[4];     // [16,512]
    float* out = (float*)d_out;                   // [8,16]

    cudaFuncSetAttribute(li_tile, cudaFuncAttributeMaxDynamicSharedMemorySize, SMEM_TOTAL);

    compact_masks<<<24, 32>>>(qm, kmm);
    norm_rows<<<B_ * SEQ_, 192>>>(qe, 0);
    norm_rows<<<KB_ * SEQ_, 192>>>(ke, 1);
    dim3 grid(KTILES, STILES, NPAIR);
    li_tile<<<grid, 256, SMEM_TOTAL>>>(alpha);
    li_combine<<<NPAIR, 128>>>(out);
}